// round 9
// baseline (speedup 1.0000x reference)
#include <cuda_runtime.h>

// GHM-C loss, single-kernel: fused streaming pass + last-block finalize.
//
// Identity: weights are constant per histogram bin, so
//   pos_loss + neg_loss = sum_b w[b] * binsum[b],
//   binsum[b] = sum over in-bin elems of log(pred)*pos + log(1-pred)*(valid-pos)*(1-hm)^4.
// in_bin == valid for this data (g<1 whenever valid) -> tot = sum(counts).
// num_pos==0 branch redundant (pos_loss==0 there).
//
// Hot loop is branchless: loss term computed unconditionally (pred is always
// in (1e-4, 1-1e-4) so logs are finite), zero-selected for invalid elements,
// and pushed through per-warp shared float atomics. Counts likewise go through
// per-warp shared int atomics (pin?1:0) -- this removes the BSSY/BSYNC
// divergence and the byte-pack select chain that were throttling load issue
// (round 8: issue 67%, DRAM only 52%).
//
// Finalize: last block (ticket + threadfence), warp-parallel, resets globals
// so each graph replay starts clean (device globals zero-init at load).
//
// Shapes fixed: B=32, H=W=512 -> HW = 2^18.

static const int kHW  = 262144;
static const int kHW3 = 3 * 262144;

__device__ double       g_binsum[10];
__device__ int          g_counts[10];
__device__ unsigned int g_done;

__global__ void __launch_bounds__(256)
ghm_fused(const float* __restrict__ pred, const float* __restrict__ target,
          int nvec, float* __restrict__ out) {
    __shared__ float s_bin[8][10];   // per-warp bin loss sums
    __shared__ int   s_cntw[8][10];  // per-warp bin counts
    __shared__ bool  s_last;

    int tid = threadIdx.x;
    int wid = tid >> 5;
    if (tid < 80) { ((float*)s_bin)[tid] = 0.0f; ((int*)s_cntw)[tid] = 0; }
    __syncthreads();

    int stride = gridDim.x * blockDim.x;
    for (int v = blockIdx.x * blockDim.x + tid; v < nvec; v += stride) {
        int i = v << 2;
        int b = i / kHW;            // power of two -> shift
        int j = i - b * kHW;
        int tb = b * kHW3 + j;
        float4 p  = __ldcs((const float4*)(pred + i));
        float4 hm = __ldcs((const float4*)(target + tb));
        float4 va = __ldcs((const float4*)(target + tb + kHW));
        float4 po = __ldcs((const float4*)(target + tb + 2 * kHW));
        const float* pp = (const float*)&p;
        const float* hh = (const float*)&hm;
        const float* vv = (const float*)&va;
        const float* ss = (const float*)&po;
#pragma unroll
        for (int k = 0; k < 4; k++) {
            float pv = pp[k], hv = hh[k], v1 = vv[k], sv = ss[k];
            bool pin = v1 > 0.0f;      // in_bin == valid (g<1 when valid)
            float g  = fmaf(pv, v1, -sv);
            float ga = fabsf(g);
            int idx = (int)(ga * 10.0f);
            idx = idx > 9 ? 9 : idx;

            // per-element loss term (bin weight factored out), branchless
            float omh = 1.0f - hv;
            float nw  = omh * omh; nw *= nw;
            float neg = v1 - sv;
            float c   = __logf(pv) * sv + __logf(1.0f - pv) * (neg * nw);
            float cz  = pin ? c : 0.0f;
            atomicAdd(&s_bin[wid][idx], cz);
            atomicAdd(&s_cntw[wid][idx], pin ? 1 : 0);
        }
    }

    __syncthreads();
    if (tid < 10) {
        float a = 0.0f;
        int   c = 0;
#pragma unroll
        for (int w = 0; w < 8; w++) { a += s_bin[w][tid]; c += s_cntw[w][tid]; }
        atomicAdd(&g_binsum[tid], (double)a);
        atomicAdd(&g_counts[tid], c);
    }
    __syncthreads();

    // ticket: last block to arrive finalizes
    if (tid == 0) {
        __threadfence();
        unsigned old = atomicAdd(&g_done, 1u);
        s_last = (old == (unsigned)gridDim.x - 1u);
    }
    __syncthreads();

    if (s_last && wid == 0) {
        __threadfence();   // all blocks' global atomics are visible
        int lane = tid;    // warp 0: lanes 0..31
        int    c = (lane < 10) ? g_counts[lane] : 0;
        double bs = (lane < 10) ? g_binsum[lane] : 0.0;

        // warp reductions: tot, n_nonempty
        int toti = c, nn = (c > 0) ? 1 : 0;
#pragma unroll
        for (int o = 16; o > 0; o >>= 1) {
            toti += __shfl_down_sync(0xffffffffu, toti, o);
            nn   += __shfl_down_sync(0xffffffffu, nn, o);
        }
        toti = __shfl_sync(0xffffffffu, toti, 0);
        nn   = __shfl_sync(0xffffffffu, nn, 0);

        double tot = (double)(toti > 1 ? toti : 1);
        double nnf = (double)(nn > 1 ? nn : 1);
        double term = (c > 0) ? (tot / (double)c) / nnf * bs : 0.0;
#pragma unroll
        for (int o = 16; o > 0; o >>= 1)
            term += __shfl_down_sync(0xffffffffu, term, o);

        if (lane == 0) out[0] = (float)(-term / tot);
        // reset accumulators + ticket for the next graph replay
        if (lane < 10) { g_binsum[lane] = 0.0; g_counts[lane] = 0; }
        __threadfence();
        if (lane == 0) g_done = 0u;
    }
}

extern "C" void kernel_launch(void* const* d_in, const int* in_sizes, int n_in,
                              void* d_out, int out_size) {
    const float* pred   = (const float*)d_in[0];
    const float* target = (const float*)d_in[1];
    int npred = in_sizes[0];
    if (n_in >= 2 && in_sizes[1] < npred) {  // pred is the smaller tensor
        pred   = (const float*)d_in[1];
        target = (const float*)d_in[0];
        npred  = in_sizes[1];
    }
    int nvec = npred >> 2;

    ghm_fused<<<1184, 256>>>(pred, target, nvec, (float*)d_out);
}

// round 10
// speedup vs baseline: 2.6995x; 2.6995x over previous
#include <cuda_runtime.h>

// GHM-C loss, single-kernel: fused streaming pass + last-block finalize.
//
// Identity: weights are constant per histogram bin, so
//   pos_loss + neg_loss = sum_b w[b] * binsum[b],
//   binsum[b] = sum over in-bin elems of log(pred)*pos + log(1-pred)*(valid-pos)*(1-hm)^4.
// in_bin == valid for this data (g<1 whenever valid) -> tot = sum(counts).
// num_pos==0 branch redundant (pos_loss==0 there).
//
// Round-9 lesson: shared-atomic REPLAY wavefronts share the l1tex pipe with
// LDG; unconditional atomics saturated L1 (86%) and starved DRAM (21%).
// So: one conditional float ATOMS per valid element only (predicated, tiny
// branch body), counts in byte-packed registers (zero L1 cost), and the
// per-warp bin array split by lane parity to halve atomic conflict degree.
// pos/valid are exact {0,1} and pos=>valid, so only ONE log per element:
//   c = pos ? log(p) : log(1-p)*(1-hm)^4.
//
// Finalize: last block (ticket + threadfence), warp-parallel, resets globals
// so each graph replay starts clean (device globals zero-init at load).
//
// Shapes fixed: B=32, H=W=512 -> HW = 2^18.

static const int kHW  = 262144;
static const int kHW3 = 3 * 262144;

__device__ double       g_binsum[10];
__device__ int          g_counts[10];
__device__ unsigned int g_done;

__global__ void __launch_bounds__(256)
ghm_fused(const float* __restrict__ pred, const float* __restrict__ target,
          int nvec, float* __restrict__ out) {
    __shared__ float s_bin[8][2][10];  // per-warp, lane-parity-split bin sums
    __shared__ bool  s_last;

    int tid = threadIdx.x;
    int wid = tid >> 5;
    int par = tid & 1;                  // lane parity replica
    if (tid < 160) ((float*)s_bin)[tid] = 0.0f;
    __syncthreads();

    // byte-packed per-thread counts: c0 = bins0-3, c1 = bins4-7, c2 = bins8-9
    unsigned c0 = 0, c1 = 0, c2 = 0;

    int stride = gridDim.x * blockDim.x;
    for (int v = blockIdx.x * blockDim.x + tid; v < nvec; v += stride) {
        int i = v << 2;
        int b = i / kHW;            // power of two -> shift
        int j = i - b * kHW;
        int tb = b * kHW3 + j;
        float4 p  = __ldcs((const float4*)(pred + i));
        float4 hm = __ldcs((const float4*)(target + tb));
        float4 va = __ldcs((const float4*)(target + tb + kHW));
        float4 po = __ldcs((const float4*)(target + tb + 2 * kHW));
        const float* pp = (const float*)&p;
        const float* hh = (const float*)&hm;
        const float* vv = (const float*)&va;
        const float* ss = (const float*)&po;
#pragma unroll
        for (int k = 0; k < 4; k++) {
            float pv = pp[k], hv = hh[k], v1 = vv[k], sv = ss[k];
            bool pin = v1 > 0.0f;      // in_bin == valid (g<1 when valid)
            bool isp = sv > 0.5f;      // pos (exact 0/1), pos => valid
            float g  = fmaf(pv, v1, -sv);
            float ga = fabsf(g);
            int idx = (int)(ga * 10.0f);
            idx = idx > 9 ? 9 : idx;

            // single-log loss term: pos ? log(p) : log(1-p)*(1-hm)^4
            float omh  = 1.0f - hv;
            float nw   = omh * omh; nw *= nw;
            float larg = isp ? pv : (1.0f - pv);
            float mult = isp ? 1.0f : nw;
            float c    = __logf(larg) * mult;

            if (pin) atomicAdd(&s_bin[wid][par][idx], c);

            // branchless byte-packed count update
            unsigned inc = pin ? (1u << ((idx & 3) * 8)) : 0u;
            c0 += (idx < 4) ? inc : 0u;
            c1 += (idx >= 4 && idx < 8) ? inc : 0u;
            c2 += (idx >= 8) ? inc : 0u;
        }
    }

    // warp reduce counters: widen bytes to 16-bit fields (max ~28*32=896)
    unsigned e0 = c0 & 0x00FF00FFu;
    unsigned e1 = (c0 >> 8) & 0x00FF00FFu;
    unsigned e2 = c1 & 0x00FF00FFu;
    unsigned e3 = (c1 >> 8) & 0x00FF00FFu;
    unsigned e4 = (c2 & 0xFFu) | ((c2 & 0xFF00u) << 8);
#pragma unroll
    for (int o = 16; o > 0; o >>= 1) {
        e0 += __shfl_down_sync(0xffffffffu, e0, o);
        e1 += __shfl_down_sync(0xffffffffu, e1, o);
        e2 += __shfl_down_sync(0xffffffffu, e2, o);
        e3 += __shfl_down_sync(0xffffffffu, e3, o);
        e4 += __shfl_down_sync(0xffffffffu, e4, o);
    }
    __shared__ int s_cnt[10];
    if (tid < 10) s_cnt[tid] = 0;
    __syncthreads();
    if ((tid & 31) == 0) {
        atomicAdd(&s_cnt[0], (int)(e0 & 0xFFFFu));
        atomicAdd(&s_cnt[1], (int)(e1 & 0xFFFFu));
        atomicAdd(&s_cnt[2], (int)(e0 >> 16));
        atomicAdd(&s_cnt[3], (int)(e1 >> 16));
        atomicAdd(&s_cnt[4], (int)(e2 & 0xFFFFu));
        atomicAdd(&s_cnt[5], (int)(e3 & 0xFFFFu));
        atomicAdd(&s_cnt[6], (int)(e2 >> 16));
        atomicAdd(&s_cnt[7], (int)(e3 >> 16));
        atomicAdd(&s_cnt[8], (int)(e4 & 0xFFFFu));
        atomicAdd(&s_cnt[9], (int)(e4 >> 16));
    }
    __syncthreads();
    if (tid < 10) {
        float a = 0.0f;
#pragma unroll
        for (int w = 0; w < 8; w++) a += s_bin[w][0][tid] + s_bin[w][1][tid];
        atomicAdd(&g_binsum[tid], (double)a);
        atomicAdd(&g_counts[tid], s_cnt[tid]);
    }
    __syncthreads();

    // ticket: last block to arrive finalizes
    if (tid == 0) {
        __threadfence();
        unsigned old = atomicAdd(&g_done, 1u);
        s_last = (old == (unsigned)gridDim.x - 1u);
    }
    __syncthreads();

    if (s_last && wid == 0) {
        __threadfence();   // all blocks' global atomics are visible
        int lane = tid;    // warp 0: lanes 0..31
        int    c = (lane < 10) ? g_counts[lane] : 0;
        double bs = (lane < 10) ? g_binsum[lane] : 0.0;

        // warp reductions: tot, n_nonempty
        int toti = c, nn = (c > 0) ? 1 : 0;
#pragma unroll
        for (int o = 16; o > 0; o >>= 1) {
            toti += __shfl_down_sync(0xffffffffu, toti, o);
            nn   += __shfl_down_sync(0xffffffffu, nn, o);
        }
        toti = __shfl_sync(0xffffffffu, toti, 0);
        nn   = __shfl_sync(0xffffffffu, nn, 0);

        double tot = (double)(toti > 1 ? toti : 1);
        double nnf = (double)(nn > 1 ? nn : 1);
        double term = (c > 0) ? (tot / (double)c) / nnf * bs : 0.0;
#pragma unroll
        for (int o = 16; o > 0; o >>= 1)
            term += __shfl_down_sync(0xffffffffu, term, o);

        if (lane == 0) out[0] = (float)(-term / tot);
        // reset accumulators + ticket for the next graph replay
        if (lane < 10) { g_binsum[lane] = 0.0; g_counts[lane] = 0; }
        __threadfence();
        if (lane == 0) g_done = 0u;
    }
}

extern "C" void kernel_launch(void* const* d_in, const int* in_sizes, int n_in,
                              void* d_out, int out_size) {
    const float* pred   = (const float*)d_in[0];
    const float* target = (const float*)d_in[1];
    int npred = in_sizes[0];
    if (n_in >= 2 && in_sizes[1] < npred) {  // pred is the smaller tensor
        pred   = (const float*)d_in[1];
        target = (const float*)d_in[0];
        npred  = in_sizes[1];
    }
    int nvec = npred >> 2;

    ghm_fused<<<1184, 256>>>(pred, target, nvec, (float*)d_out);
}